// round 7
// baseline (speedup 1.0000x reference)
#include <cuda_runtime.h>
#include <cuda_fp16.h>

// AdditiveAttention: out = softmax_k( sum_h w_v[h]*tanh(qp[q,h]+kp[k,h]) ) @ V
// B=4, Q=K=512, H=256, fp32 in/out.
// proj (f32 GEMM -> f16, smem ping-pong) -> fused(score f16x2 tanh + in-block
// softmax + PV f32). Scores held in registers; no global score buffer.

#define Bv 4
#define Qv 512
#define Kv 512
#define Hv 256
#define MROWS 2048
#define QT 4                 // queries per fused block
#define FGRID 512            // 4 batches x 128 q-tiles

__device__ uint4 g_qph[MROWS * Hv / 8];   // projected q, f16
__device__ uint4 g_kph[MROWS * Hv / 8];   // projected k, f16

__device__ __forceinline__ __half2 tanh2_ap(__half2 x) {
    unsigned xi = *(unsigned*)&x, yi;
    asm("tanh.approx.f16x2 %0, %1;" : "=r"(yi) : "r"(xi));
    return *(__half2*)&yi;
}
__device__ __forceinline__ float ex2_ap(float x) {
    float y;
    asm("ex2.approx.f32 %0, %1;" : "=f"(y) : "f"(x));
    return y;
}
__device__ __forceinline__ void cp_async16(void* smem_dst, const void* gsrc) {
    unsigned s = (unsigned)__cvta_generic_to_shared(smem_dst);
    asm volatile("cp.async.cg.shared.global [%0], [%1], 16;\n" :: "r"(s), "l"(gsrc));
}
__device__ __forceinline__ void cp_commit() {
    asm volatile("cp.async.commit_group;\n");
}
__device__ __forceinline__ __half2 u2h(unsigned u) { return *(__half2*)&u; }

// ---------------------------------------------------------------------------
// Projection GEMM: C[m,o] = sum_h A[m,h]*W[o,h], f32, f16 output.
// 64x64 tile, k-chunk 16, 4x4 microtile, reg prefetch + smem ping-pong
// (ONE __syncthreads per chunk).
// ---------------------------------------------------------------------------
__global__ __launch_bounds__(256) void proj_kernel(
    const float* __restrict__ A0, const float* __restrict__ W0, __half* __restrict__ C0,
    const float* __restrict__ A1, const float* __restrict__ W1, __half* __restrict__ C1)
{
    const float* A; const float* W; __half* C;
    if (blockIdx.z == 0) { A = A0; W = W0; C = C0; }
    else                 { A = A1; W = W1; C = C1; }

    __shared__ float As[2][16 * 68];
    __shared__ float Ws[2][16 * 68];

    const int tid = threadIdx.x;
    const int bm = blockIdx.y * 64;
    const int bn = blockIdx.x * 64;
    const int lr = tid >> 2;
    const int lc = (tid & 3) << 2;
    const int tm = (tid >> 4) << 2;
    const int tn = (tid & 15) << 2;

    const float4* A4 = (const float4*)A;
    const float4* W4 = (const float4*)W;
    const int arow = bm + lr;
    const int wrow = bn + lr;
    const int ccol = tid & 3;

    float acc[4][4];
#pragma unroll
    for (int i = 0; i < 4; i++)
#pragma unroll
        for (int j = 0; j < 4; j++) acc[i][j] = 0.f;

    float4 a = A4[arow * 64 + ccol];
    float4 w = W4[wrow * 64 + ccol];

    int p = 0;
    for (int k0 = 0; k0 < Hv; k0 += 16) {
        // store current chunk to buf[p]
        As[p][(lc + 0) * 68 + lr] = a.x; As[p][(lc + 1) * 68 + lr] = a.y;
        As[p][(lc + 2) * 68 + lr] = a.z; As[p][(lc + 3) * 68 + lr] = a.w;
        Ws[p][(lc + 0) * 68 + lr] = w.x; Ws[p][(lc + 1) * 68 + lr] = w.y;
        Ws[p][(lc + 2) * 68 + lr] = w.z; Ws[p][(lc + 3) * 68 + lr] = w.w;
        // prefetch next chunk into regs (overlaps with compute)
        if (k0 + 16 < Hv) {
            a = A4[arow * 64 + ((k0 + 16) >> 2) + ccol];
            w = W4[wrow * 64 + ((k0 + 16) >> 2) + ccol];
        }
        __syncthreads();    // buf[p] visible; also guards buf reuse (2-deep)
#pragma unroll
        for (int k = 0; k < 16; k++) {
            float4 av = *(const float4*)&As[p][k * 68 + tm];
            float4 wv = *(const float4*)&Ws[p][k * 68 + tn];
            float ar4[4] = {av.x, av.y, av.z, av.w};
            float wr4[4] = {wv.x, wv.y, wv.z, wv.w};
#pragma unroll
            for (int i = 0; i < 4; i++)
#pragma unroll
                for (int j = 0; j < 4; j++) acc[i][j] = fmaf(ar4[i], wr4[j], acc[i][j]);
        }
        p ^= 1;
    }
#pragma unroll
    for (int i = 0; i < 4; i++) {
        __half2 h0 = __floats2half2_rn(acc[i][0], acc[i][1]);
        __half2 h1 = __floats2half2_rn(acc[i][2], acc[i][3]);
        uint2 u; u.x = *(unsigned*)&h0; u.y = *(unsigned*)&h1;
        *(uint2*)&C[(bm + tm + i) * Hv + bn + tn] = u;
    }
}

// ---------------------------------------------------------------------------
// Fused score + softmax + PV. Block = 4 queries x all 512 keys, grid 512.
// 256 threads (8 warps). Score: warp w -> query w>>1, key row (w&1)*32+lane
// of each 64-key tile; 8 tile-scores per lane kept in REGISTERS.
// Softmax: per-warp reduce + warp-pair combine via smem. PV: warp w -> dim
// w*32+lane (1 f32 dim), accumulates all 4 queries; V tiles (32 keys, f32)
// double-buffered in the SAME smem as the k tiles (phases disjoint).
// smem ~72.6KB -> 3 blocks/SM.
// ---------------------------------------------------------------------------
struct FSmem {
    uint4 wvh[32];                // w_v as 256 halves (512B)
    float red[2][8];              // warp max / warp sum
    union {
        uint4 qsh[QT * 32];       // 4 q x 256 h f16 (2KB) — score phase
        float ps[QT * 512];       // probs (8KB)           — pv phase
    } qp_;
    union {
        uint4 kb[2][2048];        // 2 x (64 keys x 256 h f16)  (64KB)
        float vb[2][32 * 256];    // 2 x (32 keys x 256 d f32)  (64KB)
    } tl;
};

__device__ __forceinline__ void kb_prefetch(FSmem* sm, const uint4* ksrc,
                                            int kt, int p, int tid)
{
    const uint4* src = ksrc + (size_t)kt * 64 * 32;
#pragma unroll
    for (int j = 0; j < 8; j++) {
        int idx = j * 256 + tid;
        int r = idx >> 5, c = idx & 31;
        cp_async16(&sm->tl.kb[p][r * 32 + (c ^ (r & 31))], &src[r * 32 + c]);
    }
}

__device__ __forceinline__ void vb_prefetch(FSmem* sm, const float4* vsrc,
                                            int kt, int p, int tid)
{
    const float4* src = vsrc + (size_t)kt * 32 * 64;
#pragma unroll
    for (int j = 0; j < 8; j++) {
        int idx = j * 256 + tid;
        int r = idx >> 6, c = idx & 63;
        cp_async16(&sm->tl.vb[p][r * 256 + c * 4], &src[r * 64 + c]);
    }
}

__global__ __launch_bounds__(256, 3) void fused_kernel(
    const uint4* __restrict__ qp, const uint4* __restrict__ kp,
    const float* __restrict__ V, const float* __restrict__ wv_g,
    float* __restrict__ out)
{
    extern __shared__ char smraw[];
    FSmem* sm = (FSmem*)smraw;

    const int tid  = threadIdx.x;
    const int lane = tid & 31;
    const int w    = tid >> 5;
    const int b     = blockIdx.x >> 7;
    const int qbase = (blockIdx.x & 127) * QT;

    const uint4*  ksrc = kp + (size_t)(b * Kv) * 32;
    const float4* vsrc = (const float4*)V + (size_t)(b * Kv) * 64;

    // w_v -> f16 smem
    if (tid < 32) {
        float4 f0 = *(const float4*)&wv_g[tid * 8];
        float4 f1 = *(const float4*)&wv_g[tid * 8 + 4];
        __half2 h0 = __floats2half2_rn(f0.x, f0.y);
        __half2 h1 = __floats2half2_rn(f0.z, f0.w);
        __half2 h2 = __floats2half2_rn(f1.x, f1.y);
        __half2 h3 = __floats2half2_rn(f1.z, f1.w);
        uint4 u;
        u.x = *(unsigned*)&h0; u.y = *(unsigned*)&h1;
        u.z = *(unsigned*)&h2; u.w = *(unsigned*)&h3;
        sm->wvh[tid] = u;
    }
    // q tile (4 x 32 uint4) + k tile 0, one cp.async group
    if (tid < QT * 32) {
        const uint4* qsrc = qp + (size_t)(b * Qv + qbase) * 32;
        cp_async16(&sm->qp_.qsh[tid], &qsrc[(tid >> 5) * 32 + (tid & 31)]);
    }
    kb_prefetch(sm, ksrc, 0, 0, tid);
    cp_commit();

    const int q   = w >> 1;
    const int row = (w & 1) * 32 + lane;

    // ---------------- Score phase: 8 tiles of 64 keys ----------------
    float sc[8];
    int p = 0;
#pragma unroll 1
    for (int kt = 0; kt < 8; kt++) {
        if (kt < 7) {
            kb_prefetch(sm, ksrc, kt + 1, p ^ 1, tid);
            cp_commit();
            asm volatile("cp.async.wait_group 1;\n");
        } else {
            asm volatile("cp.async.wait_group 0;\n");
        }
        __syncthreads();

        const uint4* kb = sm->tl.kb[p];
        const uint4* qs = sm->qp_.qsh;
        float a0 = 0.f, a1 = 0.f;
#pragma unroll 4
        for (int h16 = 0; h16 < 16; h16++) {
            const int hA = 2 * h16, hB = 2 * h16 + 1;
            uint4 kuA = kb[row * 32 + (hA ^ lane)];
            uint4 kuB = kb[row * 32 + (hB ^ lane)];
            uint4 quA = qs[q * 32 + hA];
            uint4 quB = qs[q * 32 + hB];
            uint4 wuA = sm->wvh[hA];
            uint4 wuB = sm->wvh[hB];
            __half2 s0;
            s0 = __hmul2(tanh2_ap(__hadd2(u2h(quA.x), u2h(kuA.x))), u2h(wuA.x));
            s0 = __hfma2(tanh2_ap(__hadd2(u2h(quA.y), u2h(kuA.y))), u2h(wuA.y), s0);
            s0 = __hfma2(tanh2_ap(__hadd2(u2h(quA.z), u2h(kuA.z))), u2h(wuA.z), s0);
            s0 = __hfma2(tanh2_ap(__hadd2(u2h(quA.w), u2h(kuA.w))), u2h(wuA.w), s0);
            s0 = __hfma2(tanh2_ap(__hadd2(u2h(quB.x), u2h(kuB.x))), u2h(wuB.x), s0);
            s0 = __hfma2(tanh2_ap(__hadd2(u2h(quB.y), u2h(kuB.y))), u2h(wuB.y), s0);
            s0 = __hfma2(tanh2_ap(__hadd2(u2h(quB.z), u2h(kuB.z))), u2h(wuB.z), s0);
            s0 = __hfma2(tanh2_ap(__hadd2(u2h(quB.w), u2h(kuB.w))), u2h(wuB.w), s0);
            float2 f = __half22float2(s0);
            a0 += f.x; a1 += f.y;
        }
        sc[kt] = a0 + a1;
        __syncthreads();    // kb[p] free before next-next prefetch overwrites
        p ^= 1;
    }

    // ---------------- Softmax (scores in regs, warp-pair combine) ----------
    {
        const float LOG2E = 1.4426950408889634f;
        float mx = sc[0];
#pragma unroll
        for (int i = 1; i < 8; i++) mx = fmaxf(mx, sc[i]);
#pragma unroll
        for (int off = 16; off > 0; off >>= 1)
            mx = fmaxf(mx, __shfl_xor_sync(0xffffffffu, mx, off));
        if (lane == 0) sm->red[0][w] = mx;
        __syncthreads();

        // V tile 0 prefetch — k tiles fully consumed; hide load under softmax
        vb_prefetch(sm, vsrc, 0, 0, tid);
        cp_commit();

        mx = fmaxf(sm->red[0][q * 2], sm->red[0][q * 2 + 1]);
        float s = 0.f;
#pragma unroll
        for (int i = 0; i < 8; i++) {
            sc[i] = ex2_ap((sc[i] - mx) * LOG2E);
            s += sc[i];
        }
#pragma unroll
        for (int off = 16; off > 0; off >>= 1)
            s += __shfl_xor_sync(0xffffffffu, s, off);
        if (lane == 0) sm->red[1][w] = s;
        __syncthreads();
        float inv = __fdividef(1.f, sm->red[1][q * 2] + sm->red[1][q * 2 + 1]);
#pragma unroll
        for (int i = 0; i < 8; i++)
            sm->qp_.ps[q * 512 + i * 64 + row] = sc[i] * inv;
        __syncthreads();    // ps visible to all warps
    }

    // ---------------- PV: 16 tiles of 32 keys ----------------
    const int d0 = w * 32 + lane;      // this lane's output dim
    float acc[QT] = {0.f, 0.f, 0.f, 0.f};
    const float* ps = sm->qp_.ps;

    p = 0;
#pragma unroll 1
    for (int kt = 0; kt < 16; kt++) {
        if (kt < 15) {
            vb_prefetch(sm, vsrc, kt + 1, p ^ 1, tid);
            cp_commit();
            asm volatile("cp.async.wait_group 1;\n");
        } else {
            asm volatile("cp.async.wait_group 0;\n");
        }
        __syncthreads();

        const float* vt = sm->tl.vb[p];
#pragma unroll 2
        for (int kk4 = 0; kk4 < 8; kk4++) {
            float4 p0 = *(const float4*)&ps[0 * 512 + kt * 32 + kk4 * 4];
            float4 p1 = *(const float4*)&ps[1 * 512 + kt * 32 + kk4 * 4];
            float4 p2 = *(const float4*)&ps[2 * 512 + kt * 32 + kk4 * 4];
            float4 p3 = *(const float4*)&ps[3 * 512 + kt * 32 + kk4 * 4];
            float pa[4][4] = {{p0.x, p0.y, p0.z, p0.w},
                              {p1.x, p1.y, p1.z, p1.w},
                              {p2.x, p2.y, p2.z, p2.w},
                              {p3.x, p3.y, p3.z, p3.w}};
#pragma unroll
            for (int kk = 0; kk < 4; kk++) {
                float v = vt[(kk4 * 4 + kk) * 256 + d0];
                acc[0] = fmaf(pa[0][kk], v, acc[0]);
                acc[1] = fmaf(pa[1][kk], v, acc[1]);
                acc[2] = fmaf(pa[2][kk], v, acc[2]);
                acc[3] = fmaf(pa[3][kk], v, acc[3]);
            }
        }
        __syncthreads();    // vb[p] free before reuse
        p ^= 1;
    }
#pragma unroll
    for (int j = 0; j < QT; j++)
        out[(size_t)(b * Qv + qbase + j) * Hv + d0] = acc[j];
}

extern "C" void kernel_launch(void* const* d_in, const int* in_sizes, int n_in,
                              void* d_out, int out_size)
{
    const float* queries = (const float*)d_in[0];
    const float* keys    = (const float*)d_in[1];
    const float* values  = (const float*)d_in[2];
    const float* W_q     = (const float*)d_in[3];
    const float* W_k     = (const float*)d_in[4];
    const float* w_v     = (const float*)d_in[5];
    float* out = (float*)d_out;

    uint4 *qph, *kph;
    cudaGetSymbolAddress((void**)&qph, g_qph);
    cudaGetSymbolAddress((void**)&kph, g_kph);

    proj_kernel<<<dim3(4, 32, 2), 256>>>(queries, W_q, (__half*)qph,
                                         keys, W_k, (__half*)kph);

    const int smF = (int)sizeof(FSmem);
    cudaFuncSetAttribute(fused_kernel, cudaFuncAttributeMaxDynamicSharedMemorySize, smF);
    fused_kernel<<<FGRID, 256, smF>>>(qph, kph, values, w_v, out);
}

// round 8
// speedup vs baseline: 1.2782x; 1.2782x over previous
#include <cuda_runtime.h>
#include <cuda_fp16.h>

// AdditiveAttention: out = softmax_k( sum_h w_v[h]*tanh(qp[q,h]+kp[k,h]) ) @ V
// B=4, Q=K=512, H=256, fp32 in/out.
// proj (split-f16 HMMA GEMM -> f16) -> score (persistent f16x2 tanh) -> softmax+PV.

#define Bv 4
#define Qv 512
#define Kv 512
#define Hv 256
#define MROWS 2048
#define SGRID 456
#define NUNITS 2048

__device__ uint4 g_qph[MROWS * Hv / 8];   // projected q, f16
__device__ uint4 g_kph[MROWS * Hv / 8];   // projected k, f16
__device__ float g_sc[Bv * Qv * Kv];      // scores, 4MB

__device__ __forceinline__ __half2 tanh2_ap(__half2 x) {
    unsigned xi = *(unsigned*)&x, yi;
    asm("tanh.approx.f16x2 %0, %1;" : "=r"(yi) : "r"(xi));
    return *(__half2*)&yi;
}
__device__ __forceinline__ float ex2_ap(float x) {
    float y;
    asm("ex2.approx.f32 %0, %1;" : "=f"(y) : "f"(x));
    return y;
}
__device__ __forceinline__ void cp_async16(void* smem_dst, const void* gsrc) {
    unsigned s = (unsigned)__cvta_generic_to_shared(smem_dst);
    asm volatile("cp.async.cg.shared.global [%0], [%1], 16;\n" :: "r"(s), "l"(gsrc));
}
__device__ __forceinline__ void cp_commit() {
    asm volatile("cp.async.commit_group;\n");
}
__device__ __forceinline__ __half2 u2h(unsigned u) { return *(__half2*)&u; }

__device__ __forceinline__ void mma16816(float* d, const unsigned* a, const unsigned* b) {
    asm("mma.sync.aligned.m16n8k16.row.col.f32.f16.f16.f32 "
        "{%0,%1,%2,%3}, {%4,%5,%6,%7}, {%8,%9}, {%0,%1,%2,%3};"
        : "+f"(d[0]), "+f"(d[1]), "+f"(d[2]), "+f"(d[3])
        : "r"(a[0]), "r"(a[1]), "r"(a[2]), "r"(a[3]), "r"(b[0]), "r"(b[1]));
}

// ---------------------------------------------------------------------------
// Projection GEMM via HMMA: C[m,o] = sum_h A[m,h]*W[o,h], f16 output.
// Split-f16: x = hi + lo; acc += Ahi*Whi + Alo*Whi + Ahi*Wlo (f32 accum)
// -> numerically ~ f32-exact. Block 64x64, 128 threads (4 warps, each 32x32),
// k-chunk 64, smem ping-pong (1 sync/chunk).
// ---------------------------------------------------------------------------
#define PSTR 72    // smem row stride in halves

struct ProjSmem {
    __half Ahi[2][64 * PSTR];
    __half Alo[2][64 * PSTR];
    __half Whi[2][64 * PSTR];
    __half Wlo[2][64 * PSTR];
};

__global__ __launch_bounds__(128) void proj_kernel(
    const float* __restrict__ A0, const float* __restrict__ W0, __half* __restrict__ C0,
    const float* __restrict__ A1, const float* __restrict__ W1, __half* __restrict__ C1)
{
    const float* A; const float* W; __half* C;
    if (blockIdx.z == 0) { A = A0; W = W0; C = C0; }
    else                 { A = A1; W = W1; C = C1; }

    extern __shared__ char smraw[];
    ProjSmem* sm = (ProjSmem*)smraw;

    const int tid  = threadIdx.x;
    const int lane = tid & 31;
    const int wrp  = tid >> 5;
    const int bm = blockIdx.y * 64;
    const int bn = blockIdx.x * 64;
    const int warpM = (wrp >> 1) * 32;
    const int warpN = (wrp & 1) * 32;

    const float4* A4 = (const float4*)A;   // row stride 64 float4
    const float4* W4 = (const float4*)W;

    // fill indices: 1024 float4 per tile / 128 thr = 8 each
    const int fr = tid >> 4;          // base row step 8: rows fr, fr+8, ...
    const int fc = tid & 15;          // float4 col within chunk

    float acc[2][4][4];
#pragma unroll
    for (int i = 0; i < 2; i++)
#pragma unroll
        for (int j = 0; j < 4; j++)
#pragma unroll
            for (int v = 0; v < 4; v++) acc[i][j][v] = 0.f;

    float4 abuf[8], wbuf[8];
#pragma unroll
    for (int j = 0; j < 8; j++) {
        abuf[j] = A4[(bm + fr + j * 8) * 64 + fc];
        wbuf[j] = W4[(bn + fr + j * 8) * 64 + fc];
    }

    int p = 0;
    for (int ch = 0; ch < 4; ch++) {
        // split + store current chunk
#pragma unroll
        for (int j = 0; j < 8; j++) {
            int r = fr + j * 8;
            float xs[4] = {abuf[j].x, abuf[j].y, abuf[j].z, abuf[j].w};
            float ys[4] = {wbuf[j].x, wbuf[j].y, wbuf[j].z, wbuf[j].w};
#pragma unroll
            for (int v = 0; v < 4; v++) {
                __half ah = __float2half_rn(xs[v]);
                __half al = __float2half_rn(xs[v] - __half2float(ah));
                sm->Ahi[p][r * PSTR + fc * 4 + v] = ah;
                sm->Alo[p][r * PSTR + fc * 4 + v] = al;
                __half wh = __float2half_rn(ys[v]);
                __half wl = __float2half_rn(ys[v] - __half2float(wh));
                sm->Whi[p][r * PSTR + fc * 4 + v] = wh;
                sm->Wlo[p][r * PSTR + fc * 4 + v] = wl;
            }
        }
        // prefetch next chunk
        if (ch < 3) {
#pragma unroll
            for (int j = 0; j < 8; j++) {
                abuf[j] = A4[(bm + fr + j * 8) * 64 + (ch + 1) * 16 + fc];
                wbuf[j] = W4[(bn + fr + j * 8) * 64 + (ch + 1) * 16 + fc];
            }
        }
        __syncthreads();

        const __half* Ahi = sm->Ahi[p];
        const __half* Alo = sm->Alo[p];
        const __half* Whi = sm->Whi[p];
        const __half* Wlo = sm->Wlo[p];
        const int arow = warpM + (lane >> 2);
        const int kcol = (lane & 3) * 2;

#pragma unroll
        for (int ks = 0; ks < 4; ks++) {
            const int k0 = ks * 16 + kcol;
#pragma unroll
            for (int mb = 0; mb < 2; mb++) {
                const int r0 = arow + mb * 16;
                unsigned ah[4], al[4];
                ah[0] = *(const unsigned*)&Ahi[(r0    ) * PSTR + k0];
                ah[1] = *(const unsigned*)&Ahi[(r0 + 8) * PSTR + k0];
                ah[2] = *(const unsigned*)&Ahi[(r0    ) * PSTR + k0 + 8];
                ah[3] = *(const unsigned*)&Ahi[(r0 + 8) * PSTR + k0 + 8];
                al[0] = *(const unsigned*)&Alo[(r0    ) * PSTR + k0];
                al[1] = *(const unsigned*)&Alo[(r0 + 8) * PSTR + k0];
                al[2] = *(const unsigned*)&Alo[(r0    ) * PSTR + k0 + 8];
                al[3] = *(const unsigned*)&Alo[(r0 + 8) * PSTR + k0 + 8];
#pragma unroll
                for (int nb = 0; nb < 4; nb++) {
                    const int n0 = warpN + nb * 8 + (lane >> 2);
                    unsigned bh[2], bl[2];
                    bh[0] = *(const unsigned*)&Whi[n0 * PSTR + k0];
                    bh[1] = *(const unsigned*)&Whi[n0 * PSTR + k0 + 8];
                    bl[0] = *(const unsigned*)&Wlo[n0 * PSTR + k0];
                    bl[1] = *(const unsigned*)&Wlo[n0 * PSTR + k0 + 8];
                    mma16816(acc[mb][nb], ah, bh);
                    mma16816(acc[mb][nb], al, bh);
                    mma16816(acc[mb][nb], ah, bl);
                }
            }
        }
        __syncthreads();
        p ^= 1;
    }

    // store C (f16): thread holds 2x2 per (mb,nb)
    const int crow = warpM + (lane >> 2);
    const int ccol = warpN + (lane & 3) * 2;
#pragma unroll
    for (int mb = 0; mb < 2; mb++) {
#pragma unroll
        for (int nb = 0; nb < 4; nb++) {
            int r = bm + crow + mb * 16;
            int c = bn + ccol + nb * 8;
            __half2 h0 = __floats2half2_rn(acc[mb][nb][0], acc[mb][nb][1]);
            __half2 h1 = __floats2half2_rn(acc[mb][nb][2], acc[mb][nb][3]);
            *(unsigned*)&C[r * Hv + c]       = *(unsigned*)&h0;
            *(unsigned*)&C[(r + 8) * Hv + c] = *(unsigned*)&h1;
        }
    }
}

// ---------------------------------------------------------------------------
// Score kernel (persistent, unchanged from R5 best): unit = 8q x 64k.
// ---------------------------------------------------------------------------
struct ScoreSmem {
    uint4 wvh[32];
    uint4 qsh[2][256];
    uint4 kbh[2][2048];
};

__device__ __forceinline__ void score_prefetch(
    ScoreSmem* sm, const uint4* qp, const uint4* kp, int u, int p, int tid)
{
    const int qt = u >> 3;
    const int kt = u & 7;
    const int b = qt >> 6;
    const int qbase = (qt & 63) * 8;
    const uint4* qsrc = qp + (size_t)(b * Qv + qbase) * 32;
    cp_async16(&sm->qsh[p][tid], &qsrc[tid]);
    const uint4* ksrc = kp + (size_t)(b * Kv + kt * 64) * 32;
#pragma unroll
    for (int j = 0; j < 8; j++) {
        int idx = j * 256 + tid;
        int r = idx >> 5, c = idx & 31;
        cp_async16(&sm->kbh[p][r * 32 + (c ^ (r & 31))], &ksrc[r * 32 + c]);
    }
}

__global__ __launch_bounds__(256) void score_kernel(
    const uint4* __restrict__ qp, const uint4* __restrict__ kp,
    const float* __restrict__ wv_g, float* __restrict__ scores)
{
    extern __shared__ char smraw[];
    ScoreSmem* sm = (ScoreSmem*)smraw;

    const int tid  = threadIdx.x;
    const int lane = tid & 31;
    const int w    = tid >> 5;

    if (tid < 32) {
        float4 f0 = *(const float4*)&wv_g[tid * 8];
        float4 f1 = *(const float4*)&wv_g[tid * 8 + 4];
        __half2 h0 = __floats2half2_rn(f0.x, f0.y);
        __half2 h1 = __floats2half2_rn(f0.z, f0.w);
        __half2 h2 = __floats2half2_rn(f1.x, f1.y);
        __half2 h3 = __floats2half2_rn(f1.z, f1.w);
        uint4 u;
        u.x = *(unsigned*)&h0; u.y = *(unsigned*)&h1;
        u.z = *(unsigned*)&h2; u.w = *(unsigned*)&h3;
        sm->wvh[tid] = u;
    }

    const int qg   = w >> 1;
    const int rowk = (w & 1) * 32 + lane;
    const int q0   = qg * 2;

    int u = blockIdx.x;
    score_prefetch(sm, qp, kp, u, 0, tid);
    cp_commit();
    int p = 0;

    while (u < NUNITS) {
        int un = u + SGRID;
        if (un < NUNITS) {
            score_prefetch(sm, qp, kp, un, p ^ 1, tid);
            cp_commit();
            asm volatile("cp.async.wait_group 1;\n");
        } else {
            asm volatile("cp.async.wait_group 0;\n");
        }
        __syncthreads();

        const uint4* kb = sm->kbh[p];
        const uint4* qs = sm->qsh[p];
        float a00 = 0.f, a01 = 0.f, a10 = 0.f, a11 = 0.f;
#pragma unroll 4
        for (int h16 = 0; h16 < 16; h16++) {
            const int hA = 2 * h16, hB = 2 * h16 + 1;
            uint4 kuA = kb[rowk * 32 + (hA ^ lane)];
            uint4 kuB = kb[rowk * 32 + (hB ^ lane)];
            uint4 quA0 = qs[q0 * 32 + hA];
            uint4 quB0 = qs[q0 * 32 + hB];
            uint4 quA1 = qs[q0 * 32 + 32 + hA];
            uint4 quB1 = qs[q0 * 32 + 32 + hB];
            uint4 wuA = sm->wvh[hA];
            uint4 wuB = sm->wvh[hB];
            __half2 kA0 = u2h(kuA.x), kA1 = u2h(kuA.y), kA2 = u2h(kuA.z), kA3 = u2h(kuA.w);
            __half2 kB0 = u2h(kuB.x), kB1 = u2h(kuB.y), kB2 = u2h(kuB.z), kB3 = u2h(kuB.w);
            __half2 wA0 = u2h(wuA.x), wA1 = u2h(wuA.y), wA2 = u2h(wuA.z), wA3 = u2h(wuA.w);
            __half2 wB0 = u2h(wuB.x), wB1 = u2h(wuB.y), wB2 = u2h(wuB.z), wB3 = u2h(wuB.w);
            __half2 s0;
            s0 = __hmul2(tanh2_ap(__hadd2(u2h(quA0.x), kA0)), wA0);
            s0 = __hfma2(tanh2_ap(__hadd2(u2h(quA0.y), kA1)), wA1, s0);
            s0 = __hfma2(tanh2_ap(__hadd2(u2h(quA0.z), kA2)), wA2, s0);
            s0 = __hfma2(tanh2_ap(__hadd2(u2h(quA0.w), kA3)), wA3, s0);
            s0 = __hfma2(tanh2_ap(__hadd2(u2h(quB0.x), kB0)), wB0, s0);
            s0 = __hfma2(tanh2_ap(__hadd2(u2h(quB0.y), kB1)), wB1, s0);
            s0 = __hfma2(tanh2_ap(__hadd2(u2h(quB0.z), kB2)), wB2, s0);
            s0 = __hfma2(tanh2_ap(__hadd2(u2h(quB0.w), kB3)), wB3, s0);
            float2 f0 = __half22float2(s0);
            a00 += f0.x; a01 += f0.y;
            __half2 s1;
            s1 = __hmul2(tanh2_ap(__hadd2(u2h(quA1.x), kA0)), wA0);
            s1 = __hfma2(tanh2_ap(__hadd2(u2h(quA1.y), kA1)), wA1, s1);
            s1 = __hfma2(tanh2_ap(__hadd2(u2h(quA1.z), kA2)), wA2, s1);
            s1 = __hfma2(tanh2_ap(__hadd2(u2h(quA1.w), kA3)), wA3, s1);
            s1 = __hfma2(tanh2_ap(__hadd2(u2h(quB1.x), kB0)), wB0, s1);
            s1 = __hfma2(tanh2_ap(__hadd2(u2h(quB1.y), kB1)), wB1, s1);
            s1 = __hfma2(tanh2_ap(__hadd2(u2h(quB1.z), kB2)), wB2, s1);
            s1 = __hfma2(tanh2_ap(__hadd2(u2h(quB1.w), kB3)), wB3, s1);
            float2 f1 = __half22float2(s1);
            a10 += f1.x; a11 += f1.y;
        }
        {
            const int qt = u >> 3;
            const int kt = u & 7;
            const int b = qt >> 6;
            const int qbase = (qt & 63) * 8;
            const int key = kt * 64 + rowk;
            scores[(size_t)(b * Qv + qbase + q0) * Kv + key]     = a00 + a01;
            scores[(size_t)(b * Qv + qbase + q0 + 1) * Kv + key] = a10 + a11;
        }
        __syncthreads();
        u = un; p ^= 1;
    }
}

// ---------------------------------------------------------------------------
// Softmax + PV (unchanged from R5 best). Grid 128: 16 queries, 512 threads.
// ---------------------------------------------------------------------------
__global__ __launch_bounds__(512) void softmax_pv_kernel(
    const float* __restrict__ scores, const float* __restrict__ V,
    float* __restrict__ out)
{
    extern __shared__ float smB[];
    float* ps = smB;               // [16][512]
    float* vb = smB + 16 * Kv;     // [2][32][256]

    const int tid  = threadIdx.x;
    const int lane = tid & 31;
    const int w    = tid >> 5;
    const int b     = blockIdx.x >> 5;
    const int qbase = (blockIdx.x & 31) * 16;

    const float4* vsrc_base = (const float4*)V + (size_t)(b * Kv) * 64;

#pragma unroll
    for (int j = 0; j < 4; j++) {
        int idx = j * 512 + tid;
        int r = idx >> 6, c = idx & 63;
        cp_async16(&vb[r * Hv + c * 4], &vsrc_base[r * 64 + c]);
    }
    cp_commit();

    {
        const float LOG2E = 1.4426950408889634f;
        const float* src = &scores[(size_t)(b * Qv + qbase + w) * Kv];
        float4 xv[4];
        float mx = -1e30f;
#pragma unroll
        for (int j = 0; j < 4; j++) {
            xv[j] = *(const float4*)&src[j * 128 + lane * 4];
            mx = fmaxf(mx, fmaxf(fmaxf(xv[j].x, xv[j].y), fmaxf(xv[j].z, xv[j].w)));
        }
#pragma unroll
        for (int off = 16; off > 0; off >>= 1)
            mx = fmaxf(mx, __shfl_xor_sync(0xffffffffu, mx, off));
        float s = 0.f;
#pragma unroll
        for (int j = 0; j < 4; j++) {
            xv[j].x = ex2_ap((xv[j].x - mx) * LOG2E);
            xv[j].y = ex2_ap((xv[j].y - mx) * LOG2E);
            xv[j].z = ex2_ap((xv[j].z - mx) * LOG2E);
            xv[j].w = ex2_ap((xv[j].w - mx) * LOG2E);
            s += xv[j].x + xv[j].y + xv[j].z + xv[j].w;
        }
#pragma unroll
        for (int off = 16; off > 0; off >>= 1)
            s += __shfl_xor_sync(0xffffffffu, s, off);
        float inv = __fdividef(1.f, s);
#pragma unroll
        for (int j = 0; j < 4; j++) {
            xv[j].x *= inv; xv[j].y *= inv; xv[j].z *= inv; xv[j].w *= inv;
            *(float4*)&ps[w * Kv + j * 128 + lane * 4] = xv[j];
        }
    }

    const int qg  = w & 3;
    const int dof = (w >> 2) * 64 + lane * 2;

    float2 acc[4];
#pragma unroll
    for (int j = 0; j < 4; j++) acc[j] = make_float2(0.f, 0.f);

    for (int kt = 0; kt < 16; kt++) {
        if (kt < 15) {
            float* dst = vb + ((kt + 1) & 1) * 32 * Hv;
            const float4* src = vsrc_base + (size_t)(kt + 1) * 32 * 64;
#pragma unroll
            for (int j = 0; j < 4; j++) {
                int idx = j * 512 + tid;
                int r = idx >> 6, c = idx & 63;
                cp_async16(&dst[r * Hv + c * 4], &src[r * 64 + c]);
            }
            cp_commit();
            asm volatile("cp.async.wait_group 1;\n");
        } else {
            asm volatile("cp.async.wait_group 0;\n");
        }
        __syncthreads();

        const float* vt = vb + (kt & 1) * 32 * Hv;
#pragma unroll 2
        for (int kk4 = 0; kk4 < 8; kk4++) {
            float p[4][4];
#pragma unroll
            for (int j = 0; j < 4; j++) {
                float4 p4 = *(const float4*)&ps[(qg * 4 + j) * Kv + kt * 32 + kk4 * 4];
                p[j][0] = p4.x; p[j][1] = p4.y; p[j][2] = p4.z; p[j][3] = p4.w;
            }
#pragma unroll
            for (int kk = 0; kk < 4; kk++) {
                float2 v = *(const float2*)&vt[(kk4 * 4 + kk) * Hv + dof];
#pragma unroll
                for (int j = 0; j < 4; j++) {
                    acc[j].x = fmaf(p[j][kk], v.x, acc[j].x);
                    acc[j].y = fmaf(p[j][kk], v.y, acc[j].y);
                }
            }
        }
        __syncthreads();
    }
#pragma unroll
    for (int j = 0; j < 4; j++) {
        *(float2*)&out[(size_t)(b * Qv + qbase + qg * 4 + j) * Hv + dof] = acc[j];
    }
}

extern "C" void kernel_launch(void* const* d_in, const int* in_sizes, int n_in,
                              void* d_out, int out_size)
{
    const float* queries = (const float*)d_in[0];
    const float* keys    = (const float*)d_in[1];
    const float* values  = (const float*)d_in[2];
    const float* W_q     = (const float*)d_in[3];
    const float* W_k     = (const float*)d_in[4];
    const float* w_v     = (const float*)d_in[5];
    float* out = (float*)d_out;

    uint4 *qph, *kph; float* sc;
    cudaGetSymbolAddress((void**)&qph, g_qph);
    cudaGetSymbolAddress((void**)&kph, g_kph);
    cudaGetSymbolAddress((void**)&sc, g_sc);

    const int smP = (int)sizeof(ProjSmem);   // 8 * 64*72*2 = 73728 B
    cudaFuncSetAttribute(proj_kernel, cudaFuncAttributeMaxDynamicSharedMemorySize, smP);
    proj_kernel<<<dim3(4, 32, 2), 128, smP>>>(queries, W_q, (__half*)qph,
                                              keys, W_k, (__half*)kph);

    const int smA = (int)sizeof(ScoreSmem);
    cudaFuncSetAttribute(score_kernel, cudaFuncAttributeMaxDynamicSharedMemorySize, smA);
    score_kernel<<<SGRID, 256, smA>>>(qph, kph, w_v, sc);

    const int smB = (16 * Kv + 2 * 32 * Hv) * (int)sizeof(float);  // 98304 B
    cudaFuncSetAttribute(softmax_pv_kernel, cudaFuncAttributeMaxDynamicSharedMemorySize, smB);
    softmax_pv_kernel<<<128, 512, smB>>>(sc, values, out);
}